// round 13
// baseline (speedup 1.0000x reference)
#include <cuda_runtime.h>
#include <cuda_fp16.h>
#include <cstdint>

// ============================================================================
// MemristorLinear: out[B,OUT] = x[B,IN] @ W[OUT,IN]^T + bias,
//                  W[o,i] = values[w_idx[o,i]]
// B=8192, IN=4096, OUT=4096, NVAL=1024.
//
// R13: probe fp16-ACCUMULATOR HMMA (m16n8k16.f16) — on several arches the
// f32-accum legacy pipe is half-rate vs f16-accum. Segmented accumulation
// bounds the fp16 rounding: accumulate K=128 (4 iters) in f16 regs, spill
// into f32 accumulators each segment. Predicted rel_err ~5e-4.
// CTA 128x128, 8 warps (2Mx4N), 64x32 warp tiles, BK=32, 3-stage cp.async.
// ============================================================================

#define B_DIM   8192
#define IN_DIM  4096
#define OUT_DIM 4096

#define BM 128
#define BN 128
#define BK 32
#define STAGES 3
#define KITERS (IN_DIM / BK)     // 128
#define THREADS 256

#define ROWB 80                            // smem bytes/row: 64 data + 16 pad
#define PLANE_BYTES (128 * ROWB)           // 10240
#define STAGE_BYTES (2 * PLANE_BYTES)      // 20480 (A, B)
#define SMEM_BYTES  (STAGES * STAGE_BYTES) // 61440

// Scratch (allocation-free rule: __device__ globals), fp16
__device__ uint16_t g_X[(size_t)B_DIM * IN_DIM];    // 64 MB fp16 x
__device__ uint16_t g_W[(size_t)OUT_DIM * IN_DIM];  // 32 MB fp16 gathered W
__device__ uint16_t g_v16[1024];                    // fp16 codebook
__device__ int g_idx_is64;

// ---------------------------------------------------------------------------
// helpers
// ---------------------------------------------------------------------------
__device__ __forceinline__ uint32_t smem_u32(const void* p) {
    uint32_t a;
    asm("{ .reg .u64 t; cvta.to.shared.u64 t, %1; cvt.u32.u64 %0, t; }"
        : "=r"(a) : "l"(p));
    return a;
}

__device__ __forceinline__ void cp_async16(uint32_t s, const void* g) {
    asm volatile("cp.async.cg.shared.global [%0], [%1], 16;\n" :: "r"(s), "l"(g));
}

// D += A*B : m16n8k16 f16 x f16 -> f16 accumulators (2 b32 regs = 4 halves)
__device__ __forceinline__ void mma_f16h(uint32_t* c, const uint32_t* a,
                                         const uint32_t* b) {
    asm volatile(
        "mma.sync.aligned.m16n8k16.row.col.f16.f16.f16.f16 "
        "{%0,%1}, {%2,%3,%4,%5}, {%6,%7}, {%0,%1};"
        : "+r"(c[0]), "+r"(c[1])
        : "r"(a[0]), "r"(a[1]), "r"(a[2]), "r"(a[3]), "r"(b[0]), "r"(b[1]));
}

__device__ __forceinline__ uint16_t f2h(float v) {
    __half h = __float2half_rn(v);
    return *reinterpret_cast<uint16_t*>(&h);
}

// ---------------------------------------------------------------------------
// Pre-pass 0: detect w_idx dtype (indices < 1024 -> int64 odd words all 0)
// ---------------------------------------------------------------------------
__global__ void mml_detect_idx(const int* __restrict__ w32) {
    int nz = 0;
    #pragma unroll
    for (int i = 0; i < 64; i++) nz |= w32[2 * i + 1];
    g_idx_is64 = (nz == 0) ? 1 : 0;
}

// ---------------------------------------------------------------------------
// Pre-pass 1: convert the 1024-entry codebook to fp16
// ---------------------------------------------------------------------------
__global__ void mml_conv_vals(const float* __restrict__ values) {
    int t = threadIdx.x;
    g_v16[t] = f2h(values[t]);
}

// ---------------------------------------------------------------------------
// Pre-pass 2: convert x to fp16 into g_X
// ---------------------------------------------------------------------------
__global__ void mml_conv_x(const float4* __restrict__ x, int n4) {
    int t = blockIdx.x * blockDim.x + threadIdx.x;
    if (t >= n4) return;
    float4 v = x[t];
    ushort4 o;
    o.x = f2h(v.x); o.y = f2h(v.y); o.z = f2h(v.z); o.w = f2h(v.w);
    reinterpret_cast<ushort4*>(g_X)[t] = o;
}

// ---------------------------------------------------------------------------
// Pre-pass 3: gather fp16 W from the codebook
// ---------------------------------------------------------------------------
__global__ void mml_gather_w(const void* __restrict__ widx, int n4) {
    __shared__ uint16_t sv[1024];
    for (int i = threadIdx.x; i < 1024; i += blockDim.x) sv[i] = g_v16[i];
    __syncthreads();
    int t = blockIdx.x * blockDim.x + threadIdx.x;
    if (t >= n4) return;
    int i0, i1, i2, i3;
    if (g_idx_is64) {
        const longlong2* p = reinterpret_cast<const longlong2*>(widx) + 2 * t;
        longlong2 a = p[0];
        longlong2 b = p[1];
        i0 = (int)a.x; i1 = (int)a.y; i2 = (int)b.x; i3 = (int)b.y;
    } else {
        int4 a = reinterpret_cast<const int4*>(widx)[t];
        i0 = a.x; i1 = a.y; i2 = a.z; i3 = a.w;
    }
    ushort4 o;
    o.x = sv[i0]; o.y = sv[i1]; o.z = sv[i2]; o.w = sv[i3];
    reinterpret_cast<ushort4*>(g_W)[t] = o;
}

// ---------------------------------------------------------------------------
// Main GEMM: 128x128 CTA tile, 8 warps (2 M x 4 N), 64x32 warp tiles,
// fp16 m16n8k16 with f16 accumulators, segmented f32 spill every 4 iters.
// ---------------------------------------------------------------------------
__global__ __launch_bounds__(THREADS, 1)
void mml_gemm(const float* __restrict__ bias, float* __restrict__ out) {
    extern __shared__ char sm[];
    const int tid  = threadIdx.x;
    const int lane = tid & 31;
    const int wid  = tid >> 5;
    const int wm   = wid & 1;        // 2 warps in M
    const int wn   = wid >> 1;       // 4 warps in N
    const int m0   = blockIdx.y * BM;
    const int n0   = blockIdx.x * BN;

    const uint32_t smem_base = smem_u32(sm);
    const int lr = lane >> 2;        // 0..7
    const int lc = lane & 3;         // 0..3

    // f32 final accumulators + f16 segment accumulators
    float    c [4][4][4];
    uint32_t ch[4][4][2];
    #pragma unroll
    for (int mt = 0; mt < 4; mt++)
        #pragma unroll
        for (int nt = 0; nt < 4; nt++) {
            #pragma unroll
            for (int r = 0; r < 4; r++) c[mt][nt][r] = 0.0f;
            ch[mt][nt][0] = 0u; ch[mt][nt][1] = 0u;
        }

    // ---- stage loader: A + B planes, 128 rows x 64B each (fp16) ----
    auto load_stage = [&](int ks, int slot) {
        uint32_t base = smem_base + (uint32_t)(slot * STAGE_BYTES);
        const char* ga = (const char*)(g_X + (size_t)m0 * IN_DIM + (size_t)ks * BK);
        const char* gb = (const char*)(g_W + (size_t)n0 * IN_DIM + (size_t)ks * BK);
        #pragma unroll
        for (int q = tid; q < 512; q += THREADS) {      // 128 rows x 4 chunks
            int row = q >> 2, ch2 = q & 3;
            cp_async16(base + (uint32_t)(row * ROWB + ch2 * 16),
                       ga + (size_t)row * (IN_DIM * 2) + ch2 * 16);
        }
        #pragma unroll
        for (int q = tid; q < 512; q += THREADS) {
            int row = q >> 2, ch2 = q & 3;
            cp_async16(base + (uint32_t)(PLANE_BYTES + row * ROWB + ch2 * 16),
                       gb + (size_t)row * (IN_DIM * 2) + ch2 * 16);
        }
    };

    load_stage(0, 0);
    asm volatile("cp.async.commit_group;" ::: "memory");
    load_stage(1, 1);
    asm volatile("cp.async.commit_group;" ::: "memory");

    for (int i = 0; i < KITERS; i++) {
        asm volatile("cp.async.wait_group 1;" ::: "memory");
        __syncthreads();

        if (i + 2 < KITERS) load_stage(i + 2, (i + 2) % STAGES);
        asm volatile("cp.async.commit_group;" ::: "memory");

        const char* sA = sm + (i % STAGES) * STAGE_BYTES;
        const char* sB = sA + PLANE_BYTES;

        #pragma unroll
        for (int kk = 0; kk < 2; kk++) {          // two k16 chunks (32B each)
            const int kb = kk * 32 + lc * 4;
            uint32_t af[4][4], bf[4][2];
            #pragma unroll
            for (int mt = 0; mt < 4; mt++) {
                int row = wm * 64 + mt * 16 + lr;
                int o0 = row * ROWB + kb;
                int o1 = o0 + 8 * ROWB;
                af[mt][0] = *(const uint32_t*)(sA + o0);
                af[mt][1] = *(const uint32_t*)(sA + o1);
                af[mt][2] = *(const uint32_t*)(sA + o0 + 16);
                af[mt][3] = *(const uint32_t*)(sA + o1 + 16);
            }
            #pragma unroll
            for (int nt = 0; nt < 4; nt++) {
                int nrow = wn * 32 + nt * 8 + lr;
                int ob = nrow * ROWB + kb;
                bf[nt][0] = *(const uint32_t*)(sB + ob);
                bf[nt][1] = *(const uint32_t*)(sB + ob + 16);
            }
            #pragma unroll
            for (int mt = 0; mt < 4; mt++)
                #pragma unroll
                for (int nt = 0; nt < 4; nt++)
                    mma_f16h(ch[mt][nt], af[mt], bf[nt]);
        }

        // segment boundary: spill f16 accumulators into f32 every 4 iters
        if ((i & 3) == 3) {
            #pragma unroll
            for (int mt = 0; mt < 4; mt++)
                #pragma unroll
                for (int nt = 0; nt < 4; nt++) {
                    float2 lo = __half22float2(
                        *reinterpret_cast<__half2*>(&ch[mt][nt][0]));
                    float2 hi = __half22float2(
                        *reinterpret_cast<__half2*>(&ch[mt][nt][1]));
                    c[mt][nt][0] += lo.x;
                    c[mt][nt][1] += lo.y;
                    c[mt][nt][2] += hi.x;
                    c[mt][nt][3] += hi.y;
                    ch[mt][nt][0] = 0u;
                    ch[mt][nt][1] = 0u;
                }
        }
    }

    // ---- epilogue: add bias, write float2 coalesced ----
    float2 bb[4];
    #pragma unroll
    for (int nt = 0; nt < 4; nt++) {
        int cn = n0 + wn * 32 + nt * 8 + lc * 2;
        bb[nt].x = __ldg(bias + cn);
        bb[nt].y = __ldg(bias + cn + 1);
    }
    #pragma unroll
    for (int mt = 0; mt < 4; mt++) {
        int r0 = m0 + wm * 64 + mt * 16 + lr;
        int r1 = r0 + 8;
        float* o0 = out + (size_t)r0 * OUT_DIM;
        float* o1 = out + (size_t)r1 * OUT_DIM;
        #pragma unroll
        for (int nt = 0; nt < 4; nt++) {
            int cn = n0 + wn * 32 + nt * 8 + lc * 2;
            float2 v0, v1;
            v0.x = c[mt][nt][0] + bb[nt].x;
            v0.y = c[mt][nt][1] + bb[nt].y;
            v1.x = c[mt][nt][2] + bb[nt].x;
            v1.y = c[mt][nt][3] + bb[nt].y;
            *reinterpret_cast<float2*>(o0 + cn) = v0;
            *reinterpret_cast<float2*>(o1 + cn) = v1;
        }
    }
}

// ---------------------------------------------------------------------------
// kernel_launch — inputs identified by element count (order-proof):
//   x: 33554432, values: 1024, bias: 4096, w_idx: 16777216
// ---------------------------------------------------------------------------
extern "C" void kernel_launch(void* const* d_in, const int* in_sizes, int n_in,
                              void* d_out, int out_size) {
    const float* x      = nullptr;
    const float* values = nullptr;
    const float* bias   = nullptr;
    const void*  widx   = nullptr;

    for (int i = 0; i < n_in; i++) {
        switch (in_sizes[i]) {
            case 33554432: x      = (const float*)d_in[i]; break;
            case 1024:     values = (const float*)d_in[i]; break;
            case 4096:     bias   = (const float*)d_in[i]; break;
            case 16777216: widx   = d_in[i];               break;
            default: break;
        }
    }
    float* out = (float*)d_out;

    int nx4 = (B_DIM * IN_DIM) / 4;        // 8388608
    int nw4 = (OUT_DIM * IN_DIM) / 4;      // 4194304

    mml_detect_idx<<<1, 1>>>((const int*)widx);
    mml_conv_vals<<<1, 1024>>>(values);
    mml_conv_x<<<nx4 / 256, 256>>>((const float4*)x, nx4);
    mml_gather_w<<<nw4 / 256, 256>>>(widx, nw4);

    cudaFuncSetAttribute(mml_gemm, cudaFuncAttributeMaxDynamicSharedMemorySize,
                         SMEM_BYTES);
    dim3 grid(OUT_DIM / BN, B_DIM / BM);   // (32, 64)
    mml_gemm<<<grid, THREADS, SMEM_BYTES>>>(bias, out);
}

// round 14
// speedup vs baseline: 1.2903x; 1.2903x over previous
#include <cuda_runtime.h>
#include <cuda_fp16.h>
#include <cstdint>

// ============================================================================
// MemristorLinear: out[B,OUT] = x[B,IN] @ W[OUT,IN]^T + bias,
//                  W[o,i] = values[w_idx[o,i]]
// B=8192, IN=4096, OUT=4096, NVAL=1024.
//
// R14: fp16 m16n8k16 f32-accum (best: R12 1007us). Replace scalar LDS
// fragment loads with ldmatrix.x4 (4x fewer load instructions, same bytes)
// to relieve issue-slot contention with HMMA. CTA 128x256, 8 warps (2Mx4N),
// 64x64 warp tiles, BK=32, 3-stage cp.async.
// ============================================================================

#define B_DIM   8192
#define IN_DIM  4096
#define OUT_DIM 4096

#define BM 128
#define BN 256
#define BK 32
#define STAGES 3
#define KITERS (IN_DIM / BK)     // 128
#define THREADS 256

#define ROWB 80                            // smem bytes/row: 64 data + 16 pad
#define A_BYTES (128 * ROWB)               // 10240
#define B_BYTES (256 * ROWB)               // 20480
#define STAGE_BYTES (A_BYTES + B_BYTES)    // 30720
#define SMEM_BYTES  (STAGES * STAGE_BYTES) // 92160

// Scratch (allocation-free rule: __device__ globals), fp16
__device__ uint16_t g_X[(size_t)B_DIM * IN_DIM];    // 64 MB fp16 x
__device__ uint16_t g_W[(size_t)OUT_DIM * IN_DIM];  // 32 MB fp16 gathered W
__device__ uint16_t g_v16[1024];                    // fp16 codebook
__device__ int g_idx_is64;

// ---------------------------------------------------------------------------
// helpers
// ---------------------------------------------------------------------------
__device__ __forceinline__ uint32_t smem_u32(const void* p) {
    uint32_t a;
    asm("{ .reg .u64 t; cvta.to.shared.u64 t, %1; cvt.u32.u64 %0, t; }"
        : "=r"(a) : "l"(p));
    return a;
}

__device__ __forceinline__ void cp_async16(uint32_t s, const void* g) {
    asm volatile("cp.async.cg.shared.global [%0], [%1], 16;\n" :: "r"(s), "l"(g));
}

// D += A*B : m16n8k16 f16 x f16 -> f32
__device__ __forceinline__ void mma_f16(float* c, const uint32_t* a,
                                        const uint32_t* b) {
    asm volatile(
        "mma.sync.aligned.m16n8k16.row.col.f32.f16.f16.f32 "
        "{%0,%1,%2,%3}, {%4,%5,%6,%7}, {%8,%9}, {%0,%1,%2,%3};"
        : "+f"(c[0]), "+f"(c[1]), "+f"(c[2]), "+f"(c[3])
        : "r"(a[0]), "r"(a[1]), "r"(a[2]), "r"(a[3]), "r"(b[0]), "r"(b[1]));
}

// ldmatrix x4: four 8x8 b16 matrices, lane i supplies row addr of matrix i/8
#define LDSM_X4(r, addr) \
    asm volatile("ldmatrix.sync.aligned.m8n8.x4.shared.b16 " \
                 "{%0,%1,%2,%3}, [%4];" \
                 : "=r"((r)[0]), "=r"((r)[1]), "=r"((r)[2]), "=r"((r)[3]) \
                 : "r"(addr))

__device__ __forceinline__ uint16_t f2h(float v) {
    __half h = __float2half_rn(v);
    return *reinterpret_cast<uint16_t*>(&h);
}

// ---------------------------------------------------------------------------
// Pre-pass 0: detect w_idx dtype (indices < 1024 -> int64 odd words all 0)
// ---------------------------------------------------------------------------
__global__ void mml_detect_idx(const int* __restrict__ w32) {
    int nz = 0;
    #pragma unroll
    for (int i = 0; i < 64; i++) nz |= w32[2 * i + 1];
    g_idx_is64 = (nz == 0) ? 1 : 0;
}

// ---------------------------------------------------------------------------
// Pre-pass 1: convert the 1024-entry codebook to fp16
// ---------------------------------------------------------------------------
__global__ void mml_conv_vals(const float* __restrict__ values) {
    int t = threadIdx.x;
    g_v16[t] = f2h(values[t]);
}

// ---------------------------------------------------------------------------
// Pre-pass 2: convert x to fp16 into g_X
// ---------------------------------------------------------------------------
__global__ void mml_conv_x(const float4* __restrict__ x, int n4) {
    int t = blockIdx.x * blockDim.x + threadIdx.x;
    if (t >= n4) return;
    float4 v = x[t];
    ushort4 o;
    o.x = f2h(v.x); o.y = f2h(v.y); o.z = f2h(v.z); o.w = f2h(v.w);
    reinterpret_cast<ushort4*>(g_X)[t] = o;
}

// ---------------------------------------------------------------------------
// Pre-pass 3: gather fp16 W from the codebook
// ---------------------------------------------------------------------------
__global__ void mml_gather_w(const void* __restrict__ widx, int n4) {
    __shared__ uint16_t sv[1024];
    for (int i = threadIdx.x; i < 1024; i += blockDim.x) sv[i] = g_v16[i];
    __syncthreads();
    int t = blockIdx.x * blockDim.x + threadIdx.x;
    if (t >= n4) return;
    int i0, i1, i2, i3;
    if (g_idx_is64) {
        const longlong2* p = reinterpret_cast<const longlong2*>(widx) + 2 * t;
        longlong2 a = p[0];
        longlong2 b = p[1];
        i0 = (int)a.x; i1 = (int)a.y; i2 = (int)b.x; i3 = (int)b.y;
    } else {
        int4 a = reinterpret_cast<const int4*>(widx)[t];
        i0 = a.x; i1 = a.y; i2 = a.z; i3 = a.w;
    }
    ushort4 o;
    o.x = sv[i0]; o.y = sv[i1]; o.z = sv[i2]; o.w = sv[i3];
    reinterpret_cast<ushort4*>(g_W)[t] = o;
}

// ---------------------------------------------------------------------------
// Main GEMM: 128x256 CTA tile, 8 warps (2 M x 4 N), 64x64 warp tiles,
// fp16 m16n8k16, ldmatrix.x4 fragment loads, BK=32, 3-stage cp.async.
// ---------------------------------------------------------------------------
__global__ __launch_bounds__(THREADS, 1)
void mml_gemm(const float* __restrict__ bias, float* __restrict__ out) {
    extern __shared__ char sm[];
    const int tid  = threadIdx.x;
    const int lane = tid & 31;
    const int wid  = tid >> 5;
    const int wm   = wid & 1;        // 2 warps in M
    const int wn   = wid >> 1;       // 4 warps in N
    const int m0   = blockIdx.y * BM;
    const int n0   = blockIdx.x * BN;

    const uint32_t smem_base = smem_u32(sm);
    const int lr  = lane >> 2;       // 0..7 (for epilogue)
    const int lc  = lane & 3;        // 0..3
    const int g   = lane >> 3;       // ldmatrix lane-group 0..3
    const int lr8 = lane & 7;        // row within 8x8 matrix

    // per-lane ldmatrix offsets (within a stage), computed once
    // A tile mt: matrices [rows kb] [rows+8 kb] [rows kb+16] [rows+8 kb+16]
    uint32_t a_off[4], b_off[4];
    #pragma unroll
    for (int mt = 0; mt < 4; mt++) {
        int row = wm * 64 + mt * 16 + (g & 1) * 8 + lr8;
        a_off[mt] = (uint32_t)(row * ROWB + (g >> 1) * 16);
    }
    // B pair p covers nt=2p (rows p*16..+7) and nt=2p+1 (rows +8)
    #pragma unroll
    for (int p = 0; p < 4; p++) {
        int row = wn * 64 + p * 16 + (g >> 1) * 8 + lr8;
        b_off[p] = (uint32_t)(A_BYTES + row * ROWB + (g & 1) * 16);
    }

    // accumulators: 4 m-tiles x 8 n-tiles x 4 regs = 128
    float c[4][8][4];
    #pragma unroll
    for (int mt = 0; mt < 4; mt++)
        #pragma unroll
        for (int nt = 0; nt < 8; nt++)
            #pragma unroll
            for (int r = 0; r < 4; r++) c[mt][nt][r] = 0.0f;

    // ---- stage loader: A (128 rows) + B (256 rows), 64B data per row ----
    auto load_stage = [&](int ks, int slot) {
        uint32_t base = smem_base + (uint32_t)(slot * STAGE_BYTES);
        const char* ga = (const char*)(g_X + (size_t)m0 * IN_DIM + (size_t)ks * BK);
        const char* gb = (const char*)(g_W + (size_t)n0 * IN_DIM + (size_t)ks * BK);
        #pragma unroll
        for (int q = tid; q < 512; q += THREADS) {      // A: 128 rows x 4 chunks
            int row = q >> 2, ch = q & 3;
            cp_async16(base + (uint32_t)(row * ROWB + ch * 16),
                       ga + (size_t)row * (IN_DIM * 2) + ch * 16);
        }
        #pragma unroll
        for (int q = tid; q < 1024; q += THREADS) {     // B: 256 rows x 4 chunks
            int row = q >> 2, ch = q & 3;
            cp_async16(base + (uint32_t)(A_BYTES + row * ROWB + ch * 16),
                       gb + (size_t)row * (IN_DIM * 2) + ch * 16);
        }
    };

    load_stage(0, 0);
    asm volatile("cp.async.commit_group;" ::: "memory");
    load_stage(1, 1);
    asm volatile("cp.async.commit_group;" ::: "memory");

    for (int i = 0; i < KITERS; i++) {
        asm volatile("cp.async.wait_group 1;" ::: "memory");
        __syncthreads();

        if (i + 2 < KITERS) load_stage(i + 2, (i + 2) % STAGES);
        asm volatile("cp.async.commit_group;" ::: "memory");

        const uint32_t sbase = smem_base + (uint32_t)((i % STAGES) * STAGE_BYTES);

        #pragma unroll
        for (int kk = 0; kk < 2; kk++) {          // two k16 chunks (32B each)
            const uint32_t kb = kk * 32;
            uint32_t af[4][4], bf[4][4];
            #pragma unroll
            for (int mt = 0; mt < 4; mt++)
                LDSM_X4(af[mt], sbase + a_off[mt] + kb);
            #pragma unroll
            for (int p = 0; p < 4; p++)
                LDSM_X4(bf[p], sbase + b_off[p] + kb);
            #pragma unroll
            for (int mt = 0; mt < 4; mt++)
                #pragma unroll
                for (int nt = 0; nt < 8; nt++)
                    mma_f16(c[mt][nt], af[mt], &bf[nt >> 1][(nt & 1) * 2]);
        }
    }

    // ---- epilogue: add bias, write float2 coalesced ----
    float2 bb[8];
    #pragma unroll
    for (int nt = 0; nt < 8; nt++) {
        int cn = n0 + wn * 64 + nt * 8 + lc * 2;
        bb[nt].x = __ldg(bias + cn);
        bb[nt].y = __ldg(bias + cn + 1);
    }
    #pragma unroll
    for (int mt = 0; mt < 4; mt++) {
        int r0 = m0 + wm * 64 + mt * 16 + lr;
        int r1 = r0 + 8;
        float* o0 = out + (size_t)r0 * OUT_DIM;
        float* o1 = out + (size_t)r1 * OUT_DIM;
        #pragma unroll
        for (int nt = 0; nt < 8; nt++) {
            int cn = n0 + wn * 64 + nt * 8 + lc * 2;
            float2 v0, v1;
            v0.x = c[mt][nt][0] + bb[nt].x;
            v0.y = c[mt][nt][1] + bb[nt].y;
            v1.x = c[mt][nt][2] + bb[nt].x;
            v1.y = c[mt][nt][3] + bb[nt].y;
            *reinterpret_cast<float2*>(o0 + cn) = v0;
            *reinterpret_cast<float2*>(o1 + cn) = v1;
        }
    }
}

// ---------------------------------------------------------------------------
// kernel_launch — inputs identified by element count (order-proof):
//   x: 33554432, values: 1024, bias: 4096, w_idx: 16777216
// ---------------------------------------------------------------------------
extern "C" void kernel_launch(void* const* d_in, const int* in_sizes, int n_in,
                              void* d_out, int out_size) {
    const float* x      = nullptr;
    const float* values = nullptr;
    const float* bias   = nullptr;
    const void*  widx   = nullptr;

    for (int i = 0; i < n_in; i++) {
        switch (in_sizes[i]) {
            case 33554432: x      = (const float*)d_in[i]; break;
            case 1024:     values = (const float*)d_in[i]; break;
            case 4096:     bias   = (const float*)d_in[i]; break;
            case 16777216: widx   = d_in[i];               break;
            default: break;
        }
    }
    float* out = (float*)d_out;

    int nx4 = (B_DIM * IN_DIM) / 4;        // 8388608
    int nw4 = (OUT_DIM * IN_DIM) / 4;      // 4194304

    mml_detect_idx<<<1, 1>>>((const int*)widx);
    mml_conv_vals<<<1, 1024>>>(values);
    mml_conv_x<<<nx4 / 256, 256>>>((const float4*)x, nx4);
    mml_gather_w<<<nw4 / 256, 256>>>(widx, nw4);

    cudaFuncSetAttribute(mml_gemm, cudaFuncAttributeMaxDynamicSharedMemorySize,
                         SMEM_BYTES);
    dim3 grid(OUT_DIM / BN, B_DIM / BM);   // (16, 64)
    mml_gemm<<<grid, THREADS, SMEM_BYTES>>>(bias, out);
}

// round 15
// speedup vs baseline: 1.4972x; 1.1603x over previous
#include <cuda_runtime.h>
#include <cuda_fp16.h>
#include <cstdint>

// ============================================================================
// MemristorLinear: out[B,OUT] = x[B,IN] @ W[OUT,IN]^T + bias,
//                  W[o,i] = values[w_idx[o,i]]
// B=8192, IN=4096, OUT=4096, NVAL=1024.
//
// R15: fp16 m16n8k16 f32-accum + ldmatrix (R14: 981us). BK=64 halves the
// iteration count (64 iters) to amortize per-iter wait_group+syncthreads
// quanta; ldmatrix keeps the loop body ~3.4KB (fits L0 I$, unlike R9's
// scalar-LDS BK=64 attempt). CTA 128x256, 8 warps (2Mx4N), 64x64 warp
// tiles, 3-stage cp.async.
// ============================================================================

#define B_DIM   8192
#define IN_DIM  4096
#define OUT_DIM 4096

#define BM 128
#define BN 256
#define BK 64
#define STAGES 3
#define KITERS (IN_DIM / BK)     // 64
#define THREADS 256

#define ROWB 144                           // smem bytes/row: 128 data + 16 pad
#define A_BYTES (128 * ROWB)               // 18432
#define B_BYTES (256 * ROWB)               // 36864
#define STAGE_BYTES (A_BYTES + B_BYTES)    // 55296
#define SMEM_BYTES  (STAGES * STAGE_BYTES) // 165888

// Scratch (allocation-free rule: __device__ globals), fp16
__device__ uint16_t g_X[(size_t)B_DIM * IN_DIM];    // 64 MB fp16 x
__device__ uint16_t g_W[(size_t)OUT_DIM * IN_DIM];  // 32 MB fp16 gathered W
__device__ uint16_t g_v16[1024];                    // fp16 codebook
__device__ int g_idx_is64;

// ---------------------------------------------------------------------------
// helpers
// ---------------------------------------------------------------------------
__device__ __forceinline__ uint32_t smem_u32(const void* p) {
    uint32_t a;
    asm("{ .reg .u64 t; cvta.to.shared.u64 t, %1; cvt.u32.u64 %0, t; }"
        : "=r"(a) : "l"(p));
    return a;
}

__device__ __forceinline__ void cp_async16(uint32_t s, const void* g) {
    asm volatile("cp.async.cg.shared.global [%0], [%1], 16;\n" :: "r"(s), "l"(g));
}

// D += A*B : m16n8k16 f16 x f16 -> f32
__device__ __forceinline__ void mma_f16(float* c, const uint32_t* a,
                                        const uint32_t* b) {
    asm volatile(
        "mma.sync.aligned.m16n8k16.row.col.f32.f16.f16.f32 "
        "{%0,%1,%2,%3}, {%4,%5,%6,%7}, {%8,%9}, {%0,%1,%2,%3};"
        : "+f"(c[0]), "+f"(c[1]), "+f"(c[2]), "+f"(c[3])
        : "r"(a[0]), "r"(a[1]), "r"(a[2]), "r"(a[3]), "r"(b[0]), "r"(b[1]));
}

// ldmatrix x4: four 8x8 b16 matrices, lane i supplies row addr of matrix i/8
#define LDSM_X4(r, addr) \
    asm volatile("ldmatrix.sync.aligned.m8n8.x4.shared.b16 " \
                 "{%0,%1,%2,%3}, [%4];" \
                 : "=r"((r)[0]), "=r"((r)[1]), "=r"((r)[2]), "=r"((r)[3]) \
                 : "r"(addr))

__device__ __forceinline__ uint16_t f2h(float v) {
    __half h = __float2half_rn(v);
    return *reinterpret_cast<uint16_t*>(&h);
}

// ---------------------------------------------------------------------------
// Pre-pass 0: detect w_idx dtype (indices < 1024 -> int64 odd words all 0)
// ---------------------------------------------------------------------------
__global__ void mml_detect_idx(const int* __restrict__ w32) {
    int nz = 0;
    #pragma unroll
    for (int i = 0; i < 64; i++) nz |= w32[2 * i + 1];
    g_idx_is64 = (nz == 0) ? 1 : 0;
}

// ---------------------------------------------------------------------------
// Pre-pass 1: convert the 1024-entry codebook to fp16
// ---------------------------------------------------------------------------
__global__ void mml_conv_vals(const float* __restrict__ values) {
    int t = threadIdx.x;
    g_v16[t] = f2h(values[t]);
}

// ---------------------------------------------------------------------------
// Pre-pass 2: convert x to fp16 into g_X
// ---------------------------------------------------------------------------
__global__ void mml_conv_x(const float4* __restrict__ x, int n4) {
    int t = blockIdx.x * blockDim.x + threadIdx.x;
    if (t >= n4) return;
    float4 v = x[t];
    ushort4 o;
    o.x = f2h(v.x); o.y = f2h(v.y); o.z = f2h(v.z); o.w = f2h(v.w);
    reinterpret_cast<ushort4*>(g_X)[t] = o;
}

// ---------------------------------------------------------------------------
// Pre-pass 3: gather fp16 W from the codebook
// ---------------------------------------------------------------------------
__global__ void mml_gather_w(const void* __restrict__ widx, int n4) {
    __shared__ uint16_t sv[1024];
    for (int i = threadIdx.x; i < 1024; i += blockDim.x) sv[i] = g_v16[i];
    __syncthreads();
    int t = blockIdx.x * blockDim.x + threadIdx.x;
    if (t >= n4) return;
    int i0, i1, i2, i3;
    if (g_idx_is64) {
        const longlong2* p = reinterpret_cast<const longlong2*>(widx) + 2 * t;
        longlong2 a = p[0];
        longlong2 b = p[1];
        i0 = (int)a.x; i1 = (int)a.y; i2 = (int)b.x; i3 = (int)b.y;
    } else {
        int4 a = reinterpret_cast<const int4*>(widx)[t];
        i0 = a.x; i1 = a.y; i2 = a.z; i3 = a.w;
    }
    ushort4 o;
    o.x = sv[i0]; o.y = sv[i1]; o.z = sv[i2]; o.w = sv[i3];
    reinterpret_cast<ushort4*>(g_W)[t] = o;
}

// ---------------------------------------------------------------------------
// Main GEMM: 128x256 CTA tile, 8 warps (2 M x 4 N), 64x64 warp tiles,
// fp16 m16n8k16, ldmatrix.x4, BK=64 (4 k16 chunks per stage), 3-stage.
// ---------------------------------------------------------------------------
__global__ __launch_bounds__(THREADS, 1)
void mml_gemm(const float* __restrict__ bias, float* __restrict__ out) {
    extern __shared__ char sm[];
    const int tid  = threadIdx.x;
    const int lane = tid & 31;
    const int wid  = tid >> 5;
    const int wm   = wid & 1;        // 2 warps in M
    const int wn   = wid >> 1;       // 4 warps in N
    const int m0   = blockIdx.y * BM;
    const int n0   = blockIdx.x * BN;

    const uint32_t smem_base = smem_u32(sm);
    const int lr  = lane >> 2;       // 0..7 (epilogue)
    const int lc  = lane & 3;        // 0..3
    const int g   = lane >> 3;       // ldmatrix lane-group 0..3
    const int lr8 = lane & 7;        // row within 8x8 matrix

    // per-lane ldmatrix offsets (within a stage), computed once
    uint32_t a_off[4], b_off[4];
    #pragma unroll
    for (int mt = 0; mt < 4; mt++) {
        int row = wm * 64 + mt * 16 + (g & 1) * 8 + lr8;
        a_off[mt] = (uint32_t)(row * ROWB + (g >> 1) * 16);
    }
    #pragma unroll
    for (int p = 0; p < 4; p++) {
        int row = wn * 64 + p * 16 + (g >> 1) * 8 + lr8;
        b_off[p] = (uint32_t)(A_BYTES + row * ROWB + (g & 1) * 16);
    }

    // accumulators: 4 m-tiles x 8 n-tiles x 4 regs = 128
    float c[4][8][4];
    #pragma unroll
    for (int mt = 0; mt < 4; mt++)
        #pragma unroll
        for (int nt = 0; nt < 8; nt++)
            #pragma unroll
            for (int r = 0; r < 4; r++) c[mt][nt][r] = 0.0f;

    // ---- stage loader: A (128 rows) + B (256 rows), 128B data per row ----
    auto load_stage = [&](int ks, int slot) {
        uint32_t base = smem_base + (uint32_t)(slot * STAGE_BYTES);
        const char* ga = (const char*)(g_X + (size_t)m0 * IN_DIM + (size_t)ks * BK);
        const char* gb = (const char*)(g_W + (size_t)n0 * IN_DIM + (size_t)ks * BK);
        #pragma unroll
        for (int q = tid; q < 1024; q += THREADS) {     // A: 128 rows x 8 chunks
            int row = q >> 3, ch = q & 7;
            cp_async16(base + (uint32_t)(row * ROWB + ch * 16),
                       ga + (size_t)row * (IN_DIM * 2) + ch * 16);
        }
        #pragma unroll
        for (int q = tid; q < 2048; q += THREADS) {     // B: 256 rows x 8 chunks
            int row = q >> 3, ch = q & 7;
            cp_async16(base + (uint32_t)(A_BYTES + row * ROWB + ch * 16),
                       gb + (size_t)row * (IN_DIM * 2) + ch * 16);
        }
    };

    load_stage(0, 0);
    asm volatile("cp.async.commit_group;" ::: "memory");
    load_stage(1, 1);
    asm volatile("cp.async.commit_group;" ::: "memory");

    for (int i = 0; i < KITERS; i++) {
        asm volatile("cp.async.wait_group 1;" ::: "memory");
        __syncthreads();

        if (i + 2 < KITERS) load_stage(i + 2, (i + 2) % STAGES);
        asm volatile("cp.async.commit_group;" ::: "memory");

        const uint32_t sbase = smem_base + (uint32_t)((i % STAGES) * STAGE_BYTES);

        #pragma unroll
        for (int kk = 0; kk < 4; kk++) {          // four k16 chunks (32B each)
            const uint32_t kb = kk * 32;
            uint32_t af[4][4], bf[4][4];
            #pragma unroll
            for (int mt = 0; mt < 4; mt++)
                LDSM_X4(af[mt], sbase + a_off[mt] + kb);
            #pragma unroll
            for (int p = 0; p < 4; p++)
                LDSM_X4(bf[p], sbase + b_off[p] + kb);
            #pragma unroll
            for (int mt = 0; mt < 4; mt++)
                #pragma unroll
                for (int nt = 0; nt < 8; nt++)
                    mma_f16(c[mt][nt], af[mt], &bf[nt >> 1][(nt & 1) * 2]);
        }
    }

    // ---- epilogue: add bias, write float2 coalesced ----
    float2 bb[8];
    #pragma unroll
    for (int nt = 0; nt < 8; nt++) {
        int cn = n0 + wn * 64 + nt * 8 + lc * 2;
        bb[nt].x = __ldg(bias + cn);
        bb[nt].y = __ldg(bias + cn + 1);
    }
    #pragma unroll
    for (int mt = 0; mt < 4; mt++) {
        int r0 = m0 + wm * 64 + mt * 16 + lr;
        int r1 = r0 + 8;
        float* o0 = out + (size_t)r0 * OUT_DIM;
        float* o1 = out + (size_t)r1 * OUT_DIM;
        #pragma unroll
        for (int nt = 0; nt < 8; nt++) {
            int cn = n0 + wn * 64 + nt * 8 + lc * 2;
            float2 v0, v1;
            v0.x = c[mt][nt][0] + bb[nt].x;
            v0.y = c[mt][nt][1] + bb[nt].y;
            v1.x = c[mt][nt][2] + bb[nt].x;
            v1.y = c[mt][nt][3] + bb[nt].y;
            *reinterpret_cast<float2*>(o0 + cn) = v0;
            *reinterpret_cast<float2*>(o1 + cn) = v1;
        }
    }
}

// ---------------------------------------------------------------------------
// kernel_launch — inputs identified by element count (order-proof):
//   x: 33554432, values: 1024, bias: 4096, w_idx: 16777216
// ---------------------------------------------------------------------------
extern "C" void kernel_launch(void* const* d_in, const int* in_sizes, int n_in,
                              void* d_out, int out_size) {
    const float* x      = nullptr;
    const float* values = nullptr;
    const float* bias   = nullptr;
    const void*  widx   = nullptr;

    for (int i = 0; i < n_in; i++) {
        switch (in_sizes[i]) {
            case 33554432: x      = (const float*)d_in[i]; break;
            case 1024:     values = (const float*)d_in[i]; break;
            case 4096:     bias   = (const float*)d_in[i]; break;
            case 16777216: widx   = d_in[i];               break;
            default: break;
        }
    }
    float* out = (float*)d_out;

    int nx4 = (B_DIM * IN_DIM) / 4;        // 8388608
    int nw4 = (OUT_DIM * IN_DIM) / 4;      // 4194304

    mml_detect_idx<<<1, 1>>>((const int*)widx);
    mml_conv_vals<<<1, 1024>>>(values);
    mml_conv_x<<<nx4 / 256, 256>>>((const float4*)x, nx4);
    mml_gather_w<<<nw4 / 256, 256>>>(widx, nw4);

    cudaFuncSetAttribute(mml_gemm, cudaFuncAttributeMaxDynamicSharedMemorySize,
                         SMEM_BYTES);
    dim3 grid(OUT_DIM / BN, B_DIM / BM);   // (16, 64)
    mml_gemm<<<grid, THREADS, SMEM_BYTES>>>(bias, out);
}

// round 16
// speedup vs baseline: 1.6421x; 1.0968x over previous
#include <cuda_runtime.h>
#include <cuda_fp16.h>
#include <cstdint>

// ============================================================================
// MemristorLinear: out[B,OUT] = x[B,IN] @ W[OUT,IN]^T + bias,
//                  W[o,i] = values[w_idx[o,i]]
// B=8192, IN=4096, OUT=4096, NVAL=1024.
//
// R16: fp16 m16n8k16 f32-accum + ldmatrix + BK=64 (R15: 846us; ~62% tensor
// util, ~1250cyc/iter serialized barrier/LDSM phase). Shrink CTA to 128x128
// (8 warps, 64x32 warp tiles) and run 2 CTAs/SM so the co-resident CTA's
// MMA bursts fill the other's barrier/wait holes.
// ============================================================================

#define B_DIM   8192
#define IN_DIM  4096
#define OUT_DIM 4096

#define BM 128
#define BN 128
#define BK 64
#define STAGES 3
#define KITERS (IN_DIM / BK)     // 64
#define THREADS 256

#define ROWB 144                           // smem bytes/row: 128 data + 16 pad
#define A_BYTES (128 * ROWB)               // 18432
#define B_BYTES (128 * ROWB)               // 18432
#define STAGE_BYTES (A_BYTES + B_BYTES)    // 36864
#define SMEM_BYTES  (STAGES * STAGE_BYTES) // 110592 -> 2 CTAs/SM = 216 KB

// Scratch (allocation-free rule: __device__ globals), fp16
__device__ uint16_t g_X[(size_t)B_DIM * IN_DIM];    // 64 MB fp16 x
__device__ uint16_t g_W[(size_t)OUT_DIM * IN_DIM];  // 32 MB fp16 gathered W
__device__ uint16_t g_v16[1024];                    // fp16 codebook
__device__ int g_idx_is64;

// ---------------------------------------------------------------------------
// helpers
// ---------------------------------------------------------------------------
__device__ __forceinline__ uint32_t smem_u32(const void* p) {
    uint32_t a;
    asm("{ .reg .u64 t; cvta.to.shared.u64 t, %1; cvt.u32.u64 %0, t; }"
        : "=r"(a) : "l"(p));
    return a;
}

__device__ __forceinline__ void cp_async16(uint32_t s, const void* g) {
    asm volatile("cp.async.cg.shared.global [%0], [%1], 16;\n" :: "r"(s), "l"(g));
}

// D += A*B : m16n8k16 f16 x f16 -> f32
__device__ __forceinline__ void mma_f16(float* c, const uint32_t* a,
                                        const uint32_t* b) {
    asm volatile(
        "mma.sync.aligned.m16n8k16.row.col.f32.f16.f16.f32 "
        "{%0,%1,%2,%3}, {%4,%5,%6,%7}, {%8,%9}, {%0,%1,%2,%3};"
        : "+f"(c[0]), "+f"(c[1]), "+f"(c[2]), "+f"(c[3])
        : "r"(a[0]), "r"(a[1]), "r"(a[2]), "r"(a[3]), "r"(b[0]), "r"(b[1]));
}

// ldmatrix x4: four 8x8 b16 matrices, lane i supplies row addr of matrix i/8
#define LDSM_X4(r, addr) \
    asm volatile("ldmatrix.sync.aligned.m8n8.x4.shared.b16 " \
                 "{%0,%1,%2,%3}, [%4];" \
                 : "=r"((r)[0]), "=r"((r)[1]), "=r"((r)[2]), "=r"((r)[3]) \
                 : "r"(addr))

__device__ __forceinline__ uint16_t f2h(float v) {
    __half h = __float2half_rn(v);
    return *reinterpret_cast<uint16_t*>(&h);
}

// ---------------------------------------------------------------------------
// Pre-pass 0: detect w_idx dtype (indices < 1024 -> int64 odd words all 0)
// ---------------------------------------------------------------------------
__global__ void mml_detect_idx(const int* __restrict__ w32) {
    int nz = 0;
    #pragma unroll
    for (int i = 0; i < 64; i++) nz |= w32[2 * i + 1];
    g_idx_is64 = (nz == 0) ? 1 : 0;
}

// ---------------------------------------------------------------------------
// Pre-pass 1: convert the 1024-entry codebook to fp16
// ---------------------------------------------------------------------------
__global__ void mml_conv_vals(const float* __restrict__ values) {
    int t = threadIdx.x;
    g_v16[t] = f2h(values[t]);
}

// ---------------------------------------------------------------------------
// Pre-pass 2: convert x to fp16 into g_X
// ---------------------------------------------------------------------------
__global__ void mml_conv_x(const float4* __restrict__ x, int n4) {
    int t = blockIdx.x * blockDim.x + threadIdx.x;
    if (t >= n4) return;
    float4 v = x[t];
    ushort4 o;
    o.x = f2h(v.x); o.y = f2h(v.y); o.z = f2h(v.z); o.w = f2h(v.w);
    reinterpret_cast<ushort4*>(g_X)[t] = o;
}

// ---------------------------------------------------------------------------
// Pre-pass 3: gather fp16 W from the codebook
// ---------------------------------------------------------------------------
__global__ void mml_gather_w(const void* __restrict__ widx, int n4) {
    __shared__ uint16_t sv[1024];
    for (int i = threadIdx.x; i < 1024; i += blockDim.x) sv[i] = g_v16[i];
    __syncthreads();
    int t = blockIdx.x * blockDim.x + threadIdx.x;
    if (t >= n4) return;
    int i0, i1, i2, i3;
    if (g_idx_is64) {
        const longlong2* p = reinterpret_cast<const longlong2*>(widx) + 2 * t;
        longlong2 a = p[0];
        longlong2 b = p[1];
        i0 = (int)a.x; i1 = (int)a.y; i2 = (int)b.x; i3 = (int)b.y;
    } else {
        int4 a = reinterpret_cast<const int4*>(widx)[t];
        i0 = a.x; i1 = a.y; i2 = a.z; i3 = a.w;
    }
    ushort4 o;
    o.x = sv[i0]; o.y = sv[i1]; o.z = sv[i2]; o.w = sv[i3];
    reinterpret_cast<ushort4*>(g_W)[t] = o;
}

// ---------------------------------------------------------------------------
// Main GEMM: 128x128 CTA tile, 8 warps (2 M x 4 N), 64x32 warp tiles,
// fp16 m16n8k16, ldmatrix.x4, BK=64, 3-stage cp.async, 2 CTAs/SM.
// ---------------------------------------------------------------------------
__global__ __launch_bounds__(THREADS, 2)
void mml_gemm(const float* __restrict__ bias, float* __restrict__ out) {
    extern __shared__ char sm[];
    const int tid  = threadIdx.x;
    const int lane = tid & 31;
    const int wid  = tid >> 5;
    const int wm   = wid & 1;        // 2 warps in M
    const int wn   = wid >> 1;       // 4 warps in N
    const int m0   = blockIdx.y * BM;
    const int n0   = blockIdx.x * BN;

    const uint32_t smem_base = smem_u32(sm);
    const int lr  = lane >> 2;       // 0..7 (epilogue)
    const int lc  = lane & 3;        // 0..3
    const int g   = lane >> 3;       // ldmatrix lane-group 0..3
    const int lr8 = lane & 7;        // row within 8x8 matrix

    // per-lane ldmatrix offsets (within a stage), computed once
    uint32_t a_off[4], b_off[2];
    #pragma unroll
    for (int mt = 0; mt < 4; mt++) {
        int row = wm * 64 + mt * 16 + (g & 1) * 8 + lr8;
        a_off[mt] = (uint32_t)(row * ROWB + (g >> 1) * 16);
    }
    // B pair p covers nt=2p (rows p*16..+7) and nt=2p+1 (rows +8)
    #pragma unroll
    for (int p = 0; p < 2; p++) {
        int row = wn * 32 + p * 16 + (g >> 1) * 8 + lr8;
        b_off[p] = (uint32_t)(A_BYTES + row * ROWB + (g & 1) * 16);
    }

    // accumulators: 4 m-tiles x 4 n-tiles x 4 regs = 64
    float c[4][4][4];
    #pragma unroll
    for (int mt = 0; mt < 4; mt++)
        #pragma unroll
        for (int nt = 0; nt < 4; nt++)
            #pragma unroll
            for (int r = 0; r < 4; r++) c[mt][nt][r] = 0.0f;

    // ---- stage loader: A + B, 128 rows x 128B data per row each ----
    auto load_stage = [&](int ks, int slot) {
        uint32_t base = smem_base + (uint32_t)(slot * STAGE_BYTES);
        const char* ga = (const char*)(g_X + (size_t)m0 * IN_DIM + (size_t)ks * BK);
        const char* gb = (const char*)(g_W + (size_t)n0 * IN_DIM + (size_t)ks * BK);
        #pragma unroll
        for (int q = tid; q < 1024; q += THREADS) {     // A: 128 rows x 8 chunks
            int row = q >> 3, ch = q & 7;
            cp_async16(base + (uint32_t)(row * ROWB + ch * 16),
                       ga + (size_t)row * (IN_DIM * 2) + ch * 16);
        }
        #pragma unroll
        for (int q = tid; q < 1024; q += THREADS) {     // B: 128 rows x 8 chunks
            int row = q >> 3, ch = q & 7;
            cp_async16(base + (uint32_t)(A_BYTES + row * ROWB + ch * 16),
                       gb + (size_t)row * (IN_DIM * 2) + ch * 16);
        }
    };

    load_stage(0, 0);
    asm volatile("cp.async.commit_group;" ::: "memory");
    load_stage(1, 1);
    asm volatile("cp.async.commit_group;" ::: "memory");

    for (int i = 0; i < KITERS; i++) {
        asm volatile("cp.async.wait_group 1;" ::: "memory");
        __syncthreads();

        if (i + 2 < KITERS) load_stage(i + 2, (i + 2) % STAGES);
        asm volatile("cp.async.commit_group;" ::: "memory");

        const uint32_t sbase = smem_base + (uint32_t)((i % STAGES) * STAGE_BYTES);

        #pragma unroll
        for (int kk = 0; kk < 4; kk++) {          // four k16 chunks (32B each)
            const uint32_t kb = kk * 32;
            uint32_t af[4][4], bf[2][4];
            #pragma unroll
            for (int mt = 0; mt < 4; mt++)
                LDSM_X4(af[mt], sbase + a_off[mt] + kb);
            #pragma unroll
            for (int p = 0; p < 2; p++)
                LDSM_X4(bf[p], sbase + b_off[p] + kb);
            #pragma unroll
            for (int mt = 0; mt < 4; mt++)
                #pragma unroll
                for (int nt = 0; nt < 4; nt++)
                    mma_f16(c[mt][nt], af[mt], &bf[nt >> 1][(nt & 1) * 2]);
        }
    }

    // ---- epilogue: add bias, write float2 coalesced ----
    float2 bb[4];
    #pragma unroll
    for (int nt = 0; nt < 4; nt++) {
        int cn = n0 + wn * 32 + nt * 8 + lc * 2;
        bb[nt].x = __ldg(bias + cn);
        bb[nt].y = __ldg(bias + cn + 1);
    }
    #pragma unroll
    for (int mt = 0; mt < 4; mt++) {
        int r0 = m0 + wm * 64 + mt * 16 + lr;
        int r1 = r0 + 8;
        float* o0 = out + (size_t)r0 * OUT_DIM;
        float* o1 = out + (size_t)r1 * OUT_DIM;
        #pragma unroll
        for (int nt = 0; nt < 4; nt++) {
            int cn = n0 + wn * 32 + nt * 8 + lc * 2;
            float2 v0, v1;
            v0.x = c[mt][nt][0] + bb[nt].x;
            v0.y = c[mt][nt][1] + bb[nt].y;
            v1.x = c[mt][nt][2] + bb[nt].x;
            v1.y = c[mt][nt][3] + bb[nt].y;
            *reinterpret_cast<float2*>(o0 + cn) = v0;
            *reinterpret_cast<float2*>(o1 + cn) = v1;
        }
    }
}

// ---------------------------------------------------------------------------
// kernel_launch — inputs identified by element count (order-proof):
//   x: 33554432, values: 1024, bias: 4096, w_idx: 16777216
// ---------------------------------------------------------------------------
extern "C" void kernel_launch(void* const* d_in, const int* in_sizes, int n_in,
                              void* d_out, int out_size) {
    const float* x      = nullptr;
    const float* values = nullptr;
    const float* bias   = nullptr;
    const void*  widx   = nullptr;

    for (int i = 0; i < n_in; i++) {
        switch (in_sizes[i]) {
            case 33554432: x      = (const float*)d_in[i]; break;
            case 1024:     values = (const float*)d_in[i]; break;
            case 4096:     bias   = (const float*)d_in[i]; break;
            case 16777216: widx   = d_in[i];               break;
            default: break;
        }
    }
    float* out = (float*)d_out;

    int nx4 = (B_DIM * IN_DIM) / 4;        // 8388608
    int nw4 = (OUT_DIM * IN_DIM) / 4;      // 4194304

    mml_detect_idx<<<1, 1>>>((const int*)widx);
    mml_conv_vals<<<1, 1024>>>(values);
    mml_conv_x<<<nx4 / 256, 256>>>((const float4*)x, nx4);
    mml_gather_w<<<nw4 / 256, 256>>>(widx, nw4);

    cudaFuncSetAttribute(mml_gemm, cudaFuncAttributeMaxDynamicSharedMemorySize,
                         SMEM_BYTES);
    dim3 grid(OUT_DIM / BN, B_DIM / BM);   // (32, 64)
    mml_gemm<<<grid, THREADS, SMEM_BYTES>>>(bias, out);
}

// round 17
// speedup vs baseline: 1.8505x; 1.1269x over previous
#include <cuda_runtime.h>
#include <cuda_fp16.h>
#include <cstdint>

// ============================================================================
// MemristorLinear: out[B,OUT] = x[B,IN] @ W[OUT,IN]^T + bias,
//                  W[o,i] = values[w_idx[o,i]]
// B=8192, IN=4096, OUT=4096, NVAL=1024.
//
// R17: R16 structure (fp16 m16n8k16 f32-accum, ldmatrix, BK=64, CTA 128x128,
// 8 warps 2Mx4N, 3-stage cp.async, 2 CTAs/SM = 771us). Changes:
//  1. prefetch moved AFTER kk0's LDSM+MMA -> cp.async issue burst hides in
//     the MMA shadow, first LDSM starts ~130cyc earlier per iteration.
//  2. prepasses: gather uses __ldg on an L1-resident fp16 table (no smem
//     bank conflicts); codebook conversion folded into the detect kernel.
// ============================================================================

#define B_DIM   8192
#define IN_DIM  4096
#define OUT_DIM 4096

#define BM 128
#define BN 128
#define BK 64
#define STAGES 3
#define KITERS (IN_DIM / BK)     // 64
#define THREADS 256

#define ROWB 144                           // smem bytes/row: 128 data + 16 pad
#define A_BYTES (128 * ROWB)               // 18432
#define B_BYTES (128 * ROWB)               // 18432
#define STAGE_BYTES (A_BYTES + B_BYTES)    // 36864
#define SMEM_BYTES  (STAGES * STAGE_BYTES) // 110592 -> 2 CTAs/SM = 216 KB

// Scratch (allocation-free rule: __device__ globals), fp16
__device__ uint16_t g_X[(size_t)B_DIM * IN_DIM];    // 64 MB fp16 x
__device__ uint16_t g_W[(size_t)OUT_DIM * IN_DIM];  // 32 MB fp16 gathered W
__device__ uint16_t g_v16[1024];                    // fp16 codebook
__device__ int g_idx_is64;

// ---------------------------------------------------------------------------
// helpers
// ---------------------------------------------------------------------------
__device__ __forceinline__ uint32_t smem_u32(const void* p) {
    uint32_t a;
    asm("{ .reg .u64 t; cvta.to.shared.u64 t, %1; cvt.u32.u64 %0, t; }"
        : "=r"(a) : "l"(p));
    return a;
}

__device__ __forceinline__ void cp_async16(uint32_t s, const void* g) {
    asm volatile("cp.async.cg.shared.global [%0], [%1], 16;\n" :: "r"(s), "l"(g));
}

// D += A*B : m16n8k16 f16 x f16 -> f32
__device__ __forceinline__ void mma_f16(float* c, const uint32_t* a,
                                        const uint32_t* b) {
    asm volatile(
        "mma.sync.aligned.m16n8k16.row.col.f32.f16.f16.f32 "
        "{%0,%1,%2,%3}, {%4,%5,%6,%7}, {%8,%9}, {%0,%1,%2,%3};"
        : "+f"(c[0]), "+f"(c[1]), "+f"(c[2]), "+f"(c[3])
        : "r"(a[0]), "r"(a[1]), "r"(a[2]), "r"(a[3]), "r"(b[0]), "r"(b[1]));
}

// ldmatrix x4: four 8x8 b16 matrices, lane i supplies row addr of matrix i/8
#define LDSM_X4(r, addr) \
    asm volatile("ldmatrix.sync.aligned.m8n8.x4.shared.b16 " \
                 "{%0,%1,%2,%3}, [%4];" \
                 : "=r"((r)[0]), "=r"((r)[1]), "=r"((r)[2]), "=r"((r)[3]) \
                 : "r"(addr))

__device__ __forceinline__ uint16_t f2h(float v) {
    __half h = __float2half_rn(v);
    return *reinterpret_cast<uint16_t*>(&h);
}

// ---------------------------------------------------------------------------
// Pre-pass 0: detect w_idx dtype + convert codebook (1024 threads)
// ---------------------------------------------------------------------------
__global__ void mml_prep(const int* __restrict__ w32,
                         const float* __restrict__ values) {
    int t = threadIdx.x;
    g_v16[t] = f2h(values[t]);
    if (t == 0) {
        int nz = 0;
        #pragma unroll
        for (int i = 0; i < 64; i++) nz |= w32[2 * i + 1];
        g_idx_is64 = (nz == 0) ? 1 : 0;
    }
}

// ---------------------------------------------------------------------------
// Pre-pass 1: convert x to fp16 into g_X
// ---------------------------------------------------------------------------
__global__ void mml_conv_x(const float4* __restrict__ x, int n4) {
    int t = blockIdx.x * blockDim.x + threadIdx.x;
    if (t >= n4) return;
    float4 v = x[t];
    ushort4 o;
    o.x = f2h(v.x); o.y = f2h(v.y); o.z = f2h(v.z); o.w = f2h(v.w);
    reinterpret_cast<ushort4*>(g_X)[t] = o;
}

// ---------------------------------------------------------------------------
// Pre-pass 2: gather fp16 W from the codebook (L1-resident __ldg table)
// ---------------------------------------------------------------------------
__global__ void mml_gather_w(const void* __restrict__ widx, int n4) {
    int t = blockIdx.x * blockDim.x + threadIdx.x;
    if (t >= n4) return;
    int i0, i1, i2, i3;
    if (g_idx_is64) {
        const longlong2* p = reinterpret_cast<const longlong2*>(widx) + 2 * t;
        longlong2 a = p[0];
        longlong2 b = p[1];
        i0 = (int)a.x; i1 = (int)a.y; i2 = (int)b.x; i3 = (int)b.y;
    } else {
        int4 a = reinterpret_cast<const int4*>(widx)[t];
        i0 = a.x; i1 = a.y; i2 = a.z; i3 = a.w;
    }
    ushort4 o;
    o.x = __ldg(g_v16 + i0);
    o.y = __ldg(g_v16 + i1);
    o.z = __ldg(g_v16 + i2);
    o.w = __ldg(g_v16 + i3);
    reinterpret_cast<ushort4*>(g_W)[t] = o;
}

// ---------------------------------------------------------------------------
// Main GEMM: 128x128 CTA tile, 8 warps (2 M x 4 N), 64x32 warp tiles,
// fp16 m16n8k16, ldmatrix.x4, BK=64, 3-stage cp.async, 2 CTAs/SM.
// Prefetch issues AFTER the first kk chunk (in the MMA shadow).
// ---------------------------------------------------------------------------
__global__ __launch_bounds__(THREADS, 2)
void mml_gemm(const float* __restrict__ bias, float* __restrict__ out) {
    extern __shared__ char sm[];
    const int tid  = threadIdx.x;
    const int lane = tid & 31;
    const int wid  = tid >> 5;
    const int wm   = wid & 1;        // 2 warps in M
    const int wn   = wid >> 1;       // 4 warps in N
    const int m0   = blockIdx.y * BM;
    const int n0   = blockIdx.x * BN;

    const uint32_t smem_base = smem_u32(sm);
    const int lr  = lane >> 2;       // 0..7 (epilogue)
    const int lc  = lane & 3;        // 0..3
    const int g   = lane >> 3;       // ldmatrix lane-group 0..3
    const int lr8 = lane & 7;        // row within 8x8 matrix

    // per-lane ldmatrix offsets (within a stage), computed once
    uint32_t a_off[4], b_off[2];
    #pragma unroll
    for (int mt = 0; mt < 4; mt++) {
        int row = wm * 64 + mt * 16 + (g & 1) * 8 + lr8;
        a_off[mt] = (uint32_t)(row * ROWB + (g >> 1) * 16);
    }
    #pragma unroll
    for (int p = 0; p < 2; p++) {
        int row = wn * 32 + p * 16 + (g >> 1) * 8 + lr8;
        b_off[p] = (uint32_t)(A_BYTES + row * ROWB + (g & 1) * 16);
    }

    // accumulators: 4 m-tiles x 4 n-tiles x 4 regs = 64
    float c[4][4][4];
    #pragma unroll
    for (int mt = 0; mt < 4; mt++)
        #pragma unroll
        for (int nt = 0; nt < 4; nt++)
            #pragma unroll
            for (int r = 0; r < 4; r++) c[mt][nt][r] = 0.0f;

    // ---- stage loader: A + B, 128 rows x 128B data per row each ----
    auto load_stage = [&](int ks, int slot) {
        uint32_t base = smem_base + (uint32_t)(slot * STAGE_BYTES);
        const char* ga = (const char*)(g_X + (size_t)m0 * IN_DIM + (size_t)ks * BK);
        const char* gb = (const char*)(g_W + (size_t)n0 * IN_DIM + (size_t)ks * BK);
        #pragma unroll
        for (int q = tid; q < 1024; q += THREADS) {     // A: 128 rows x 8 chunks
            int row = q >> 3, ch = q & 7;
            cp_async16(base + (uint32_t)(row * ROWB + ch * 16),
                       ga + (size_t)row * (IN_DIM * 2) + ch * 16);
        }
        #pragma unroll
        for (int q = tid; q < 1024; q += THREADS) {     // B: 128 rows x 8 chunks
            int row = q >> 3, ch = q & 7;
            cp_async16(base + (uint32_t)(A_BYTES + row * ROWB + ch * 16),
                       gb + (size_t)row * (IN_DIM * 2) + ch * 16);
        }
    };

    // one kk chunk: 6 LDSM.x4 + 16 HMMA
    auto do_kk = [&](uint32_t sbase, int kk) {
        const uint32_t kb = (uint32_t)(kk * 32);
        uint32_t af[4][4], bf[2][4];
        #pragma unroll
        for (int mt = 0; mt < 4; mt++)
            LDSM_X4(af[mt], sbase + a_off[mt] + kb);
        #pragma unroll
        for (int p = 0; p < 2; p++)
            LDSM_X4(bf[p], sbase + b_off[p] + kb);
        #pragma unroll
        for (int mt = 0; mt < 4; mt++)
            #pragma unroll
            for (int nt = 0; nt < 4; nt++)
                mma_f16(c[mt][nt], af[mt], &bf[nt >> 1][(nt & 1) * 2]);
    };

    load_stage(0, 0);
    asm volatile("cp.async.commit_group;" ::: "memory");
    load_stage(1, 1);
    asm volatile("cp.async.commit_group;" ::: "memory");

    for (int i = 0; i < KITERS; i++) {
        asm volatile("cp.async.wait_group 1;" ::: "memory");
        __syncthreads();

        const uint32_t sbase = smem_base + (uint32_t)((i % STAGES) * STAGE_BYTES);

        // kk0 first: LDSM+MMA start immediately after the barrier
        do_kk(sbase, 0);

        // prefetch stage i+2 in the MMA shadow
        if (i + 2 < KITERS) load_stage(i + 2, (i + 2) % STAGES);
        asm volatile("cp.async.commit_group;" ::: "memory");

        do_kk(sbase, 1);
        do_kk(sbase, 2);
        do_kk(sbase, 3);
    }

    // ---- epilogue: add bias, write float2 coalesced ----
    float2 bb[4];
    #pragma unroll
    for (int nt = 0; nt < 4; nt++) {
        int cn = n0 + wn * 32 + nt * 8 + lc * 2;
        bb[nt].x = __ldg(bias + cn);
        bb[nt].y = __ldg(bias + cn + 1);
    }
    #pragma unroll
    for (int mt = 0; mt < 4; mt++) {
        int r0 = m0 + wm * 64 + mt * 16 + lr;
        int r1 = r0 + 8;
        float* o0 = out + (size_t)r0 * OUT_DIM;
        float* o1 = out + (size_t)r1 * OUT_DIM;
        #pragma unroll
        for (int nt = 0; nt < 4; nt++) {
            int cn = n0 + wn * 32 + nt * 8 + lc * 2;
            float2 v0, v1;
            v0.x = c[mt][nt][0] + bb[nt].x;
            v0.y = c[mt][nt][1] + bb[nt].y;
            v1.x = c[mt][nt][2] + bb[nt].x;
            v1.y = c[mt][nt][3] + bb[nt].y;
            *reinterpret_cast<float2*>(o0 + cn) = v0;
            *reinterpret_cast<float2*>(o1 + cn) = v1;
        }
    }
}

// ---------------------------------------------------------------------------
// kernel_launch — inputs identified by element count (order-proof):
//   x: 33554432, values: 1024, bias: 4096, w_idx: 16777216
// ---------------------------------------------------------------------------
extern "C" void kernel_launch(void* const* d_in, const int* in_sizes, int n_in,
                              void* d_out, int out_size) {
    const float* x      = nullptr;
    const float* values = nullptr;
    const float* bias   = nullptr;
    const void*  widx   = nullptr;

    for (int i = 0; i < n_in; i++) {
        switch (in_sizes[i]) {
            case 33554432: x      = (const float*)d_in[i]; break;
            case 1024:     values = (const float*)d_in[i]; break;
            case 4096:     bias   = (const float*)d_in[i]; break;
            case 16777216: widx   = d_in[i];               break;
            default: break;
        }
    }
    float* out = (float*)d_out;

    int nx4 = (B_DIM * IN_DIM) / 4;        // 8388608
    int nw4 = (OUT_DIM * IN_DIM) / 4;      // 4194304

    mml_prep<<<1, 1024>>>((const int*)widx, values);
    mml_conv_x<<<nx4 / 256, 256>>>((const float4*)x, nx4);
    mml_gather_w<<<nw4 / 256, 256>>>(widx, nw4);

    cudaFuncSetAttribute(mml_gemm, cudaFuncAttributeMaxDynamicSharedMemorySize,
                         SMEM_BYTES);
    dim3 grid(OUT_DIM / BN, B_DIM / BM);   // (32, 64)
    mml_gemm<<<grid, THREADS, SMEM_BYTES>>>(bias, out);
}